// round 16
// baseline (speedup 1.0000x reference)
#include <cuda_runtime.h>
#include <cuda_fp16.h>
#include <math.h>

#define NN   100000
#define M3   3
#define DIN  128
#define DH   64
#define NE   1600000
#define NP   300000                     // M3*NN rows
#define NET  4800000                    // M3*NE edges
#define SCAN_CHUNK 2048
#define SCAN_NBLK  147                  // ceil(NP/2048)

// ---- scratch (static device allocations; no cudaMalloc allowed) ----
__device__ __half g_projh[(size_t)NP * DH];      // [p][h] fp16
__device__ __half g_hh [(size_t)NP * DH];        // post-prelu h (fp16, feeds z)
__device__ int   g_cnt [NP];
__device__ int   g_rowStart[NP];
__device__ int   g_cursor[NP];
__device__ int   g_eidx[NET];
__device__ int   g_blockSums[SCAN_NBLK];
__device__ int   g_blockOff [SCAN_NBLK];
__device__ float g_logits[M3];
__device__ float g_beta[M3];

__device__ __forceinline__ float tanh_fast(float x) {
    float y;
    asm("tanh.approx.f32 %0, %1;" : "=f"(y) : "f"(x));
    return y;
}

// ---------------------------------------------------------------------------
// Kernel 0: zero counters + logits
// ---------------------------------------------------------------------------
__global__ void zero_kernel() {
    int i = blockIdx.x * blockDim.x + threadIdx.x;
    if (i < NP) g_cnt[i] = 0;
    if (i < M3) g_logits[i] = 0.f;
}

// ---------------------------------------------------------------------------
// Kernel 1: proj via fp16 MMA (fp32 accum, fp16 out). 4 warps, 64x64 tile.
// ---------------------------------------------------------------------------
__global__ __launch_bounds__(128) void proj_mma_kernel(const float* __restrict__ feats,
                                                       const float* __restrict__ W) {
    __shared__ __align__(16) __half sA[64 * 136];
    __shared__ __align__(16) __half sW[128 * 72];
    const int m  = blockIdx.y;
    const int n0 = blockIdx.x * 64;
    const int tid = threadIdx.x;
    const int wid = tid >> 5, lane = tid & 31;
    const float* fbase = feats + (size_t)m * NN * DIN;
    const float* wbase = W + (size_t)m * DIN * DH;

    for (int i = tid; i < 64 * 64; i += 128) {
        int r = i >> 6, c2 = i & 63;
        float2 v = make_float2(0.f, 0.f);
        if (n0 + r < NN) v = *(const float2*)&fbase[(size_t)(n0 + r) * DIN + c2 * 2];
        *(__half2*)&sA[r * 136 + c2 * 2] = __floats2half2_rn(v.x, v.y);
    }
    for (int i = tid; i < 128 * 32; i += 128) {
        int r = i >> 5, c2 = i & 31;
        float2 v = *(const float2*)&wbase[(size_t)r * DH + c2 * 2];
        *(__half2*)&sW[r * 72 + c2 * 2] = __floats2half2_rn(v.x, v.y);
    }
    __syncthreads();

    float c[8][4] = {};
    const int rowBase = wid * 16;
    unsigned aBase = (unsigned)__cvta_generic_to_shared(sA);
    unsigned wBase = (unsigned)__cvta_generic_to_shared(sW);

#pragma unroll
    for (int k0 = 0; k0 < 128; k0 += 16) {
        unsigned a0, a1, a2, a3;
        unsigned aAddr = aBase + (unsigned)(((rowBase + (lane & 15)) * 136 + k0 + ((lane >> 4) * 8)) * 2);
        asm volatile("ldmatrix.sync.aligned.m8n8.x4.shared.b16 {%0,%1,%2,%3}, [%4];"
                     : "=r"(a0), "=r"(a1), "=r"(a2), "=r"(a3) : "r"(aAddr));
#pragma unroll
        for (int nt = 0; nt < 8; nt++) {
            unsigned b0, b1;
            unsigned bAddr = wBase + (unsigned)(((k0 + (lane & 15)) * 72 + nt * 8) * 2);
            asm volatile("ldmatrix.sync.aligned.m8n8.x2.trans.shared.b16 {%0,%1}, [%2];"
                         : "=r"(b0), "=r"(b1) : "r"(bAddr));
            asm volatile("mma.sync.aligned.m16n8k16.row.col.f32.f16.f16.f32 "
                         "{%0,%1,%2,%3}, {%4,%5,%6,%7}, {%8,%9}, {%0,%1,%2,%3};"
                         : "+f"(c[nt][0]), "+f"(c[nt][1]), "+f"(c[nt][2]), "+f"(c[nt][3])
                         : "r"(a0), "r"(a1), "r"(a2), "r"(a3), "r"(b0), "r"(b1));
        }
    }

    int groupID = lane >> 2, tig = lane & 3;
    int r0 = n0 + rowBase + groupID;
    int r1 = r0 + 8;
#pragma unroll
    for (int nt = 0; nt < 8; nt++) {
        int col = nt * 8 + tig * 2;
        if (r0 < NN)
            *(__half2*)&g_projh[((size_t)m * NN + r0) * DH + col] = __floats2half2_rn(c[nt][0], c[nt][1]);
        if (r1 < NN)
            *(__half2*)&g_projh[((size_t)m * NN + r1) * DH + col] = __floats2half2_rn(c[nt][2], c[nt][3]);
    }
}

// ---------------------------------------------------------------------------
// Kernel 2a: histogram of dst
// ---------------------------------------------------------------------------
__global__ __launch_bounds__(256) void hist_kernel(const int* __restrict__ dst) {
    int gid = blockIdx.x * blockDim.x + threadIdx.x;
    if (gid >= NET) return;
    int m = gid / NE;
    atomicAdd(&g_cnt[m * NN + dst[gid]], 1);
}

// ---------------------------------------------------------------------------
// Kernel 2b: per-chunk sums
// ---------------------------------------------------------------------------
__global__ __launch_bounds__(256) void scan1_kernel() {
    __shared__ int s[256];
    int tid = threadIdx.x;
    int base = blockIdx.x * SCAN_CHUNK + tid * 8;
    int sum = 0;
#pragma unroll
    for (int j = 0; j < 8; j++) {
        int i = base + j;
        if (i < NP) sum += g_cnt[i];
    }
    s[tid] = sum; __syncthreads();
    for (int off = 128; off; off >>= 1) {
        if (tid < off) s[tid] += s[tid + off];
        __syncthreads();
    }
    if (tid == 0) g_blockSums[blockIdx.x] = s[0];
}

// ---------------------------------------------------------------------------
// Kernel 2c: exclusive scan of 147 chunk sums — Hillis-Steele
// ---------------------------------------------------------------------------
__global__ __launch_bounds__(192) void scan2_kernel() {
    __shared__ int s[192];
    int tid = threadIdx.x;
    int v = (tid < SCAN_NBLK) ? g_blockSums[tid] : 0;
    s[tid] = v; __syncthreads();
    for (int off = 1; off < 192; off <<= 1) {
        int add = (tid >= off) ? s[tid - off] : 0;
        __syncthreads();
        s[tid] += add;
        __syncthreads();
    }
    if (tid < SCAN_NBLK) g_blockOff[tid] = s[tid] - v;   // exclusive
}

// ---------------------------------------------------------------------------
// Kernel 2d: per-chunk exclusive scan -> rowStart, cursor
// ---------------------------------------------------------------------------
__global__ __launch_bounds__(256) void scan3_kernel() {
    __shared__ int s[256];
    int tid = threadIdx.x;
    int base = blockIdx.x * SCAN_CHUNK + tid * 8;
    int cnt8[8];
    int sum = 0;
#pragma unroll
    for (int j = 0; j < 8; j++) {
        int i = base + j;
        cnt8[j] = (i < NP) ? g_cnt[i] : 0;
        sum += cnt8[j];
    }
    s[tid] = sum; __syncthreads();
    for (int off = 1; off < 256; off <<= 1) {
        int add = (tid >= off) ? s[tid - off] : 0;
        __syncthreads();
        s[tid] += add;
        __syncthreads();
    }
    int run = g_blockOff[blockIdx.x] + s[tid] - sum;
#pragma unroll
    for (int j = 0; j < 8; j++) {
        int i = base + j;
        if (i < NP) { g_rowStart[i] = run; g_cursor[i] = run; }
        run += cnt8[j];
    }
}

// ---------------------------------------------------------------------------
// Kernel 2e: fill buckets
// ---------------------------------------------------------------------------
__global__ __launch_bounds__(256) void fill_kernel(const int* __restrict__ src,
                                                   const int* __restrict__ dst) {
    int gid = blockIdx.x * blockDim.x + threadIdx.x;
    if (gid >= NET) return;
    int m = gid / NE;
    int pos = atomicAdd(&g_cursor[m * NN + dst[gid]], 1);
    g_eidx[pos] = m * NN + src[gid];
}

// ---------------------------------------------------------------------------
// Kernel 3: FUSED aggregate + finalize. 512 threads, 64 nodes/block.
// Phase 1 (all threads, 8/node): gather fp16 proj rows, compute
// h = prelu(agg/deg + b), write to smem tile + g_hh (for z).
// Phase 2 (warps 0-3): h @ fcW via fp16 MMA; tanh; dot attn; logits atomics.
// ---------------------------------------------------------------------------
__global__ __launch_bounds__(512) void aggfin_kernel(const float* __restrict__ b,
                                                     const float* __restrict__ prelu_a,
                                                     const float* __restrict__ fc_W,
                                                     const float* __restrict__ fc_b,
                                                     const float* __restrict__ attn) {
    __shared__ __align__(16) __half sH[64 * 72];
    __shared__ __align__(16) __half sW[64 * 72];
    __shared__ float sLog[2];
    const int tid = threadIdx.x;
    const int wid = tid >> 5, lane = tid & 31;
    const long long p0 = (long long)blockIdx.x * 64;
    const int m0 = (int)(p0 / NN);

    // stage fc_W
    for (int i = tid; i < 64 * 32; i += 512) {
        int r = i >> 5, c2 = i & 31;
        float2 v = *(const float2*)&fc_W[r * DH + c2 * 2];
        *(__half2*)&sW[r * 72 + c2 * 2] = __floats2half2_rn(v.x, v.y);
    }
    if (tid < 2) sLog[tid] = 0.f;

    // ---- phase 1: aggregate 64 nodes (8 threads each) ----
    {
        int r    = tid >> 3;            // local node 0..63
        int part = tid & 7;             // owns cols [part*8, part*8+8)
        long long pl = p0 + r;
        __half2 ph[4];
        if (pl < NP) {
            int p = (int)pl;
            int rs = g_rowStart[p];
            int c  = g_cnt[p];
            float acc[8] = {};
            int e = rs, re = rs + c;
            for (; e + 1 < re; e += 2) {
                int i0 = g_eidx[e], i1 = g_eidx[e + 1];
                uint4 r0 = *(const uint4*)&g_projh[(size_t)i0 * DH + part * 8];
                uint4 r1 = *(const uint4*)&g_projh[(size_t)i1 * DH + part * 8];
                float2 t;
                t = __half22float2(*(__half2*)&r0.x); acc[0] += t.x; acc[1] += t.y;
                t = __half22float2(*(__half2*)&r0.y); acc[2] += t.x; acc[3] += t.y;
                t = __half22float2(*(__half2*)&r0.z); acc[4] += t.x; acc[5] += t.y;
                t = __half22float2(*(__half2*)&r0.w); acc[6] += t.x; acc[7] += t.y;
                t = __half22float2(*(__half2*)&r1.x); acc[0] += t.x; acc[1] += t.y;
                t = __half22float2(*(__half2*)&r1.y); acc[2] += t.x; acc[3] += t.y;
                t = __half22float2(*(__half2*)&r1.z); acc[4] += t.x; acc[5] += t.y;
                t = __half22float2(*(__half2*)&r1.w); acc[6] += t.x; acc[7] += t.y;
            }
            if (e < re) {
                int i0 = g_eidx[e];
                uint4 r0 = *(const uint4*)&g_projh[(size_t)i0 * DH + part * 8];
                float2 t;
                t = __half22float2(*(__half2*)&r0.x); acc[0] += t.x; acc[1] += t.y;
                t = __half22float2(*(__half2*)&r0.y); acc[2] += t.x; acc[3] += t.y;
                t = __half22float2(*(__half2*)&r0.z); acc[4] += t.x; acc[5] += t.y;
                t = __half22float2(*(__half2*)&r0.w); acc[6] += t.x; acc[7] += t.y;
            }
            int m = p / NN;
            float inv = 1.0f / (float)max(c, 1);
            float a = prelu_a[m];
            float4 b0 = *(const float4*)&b[m * DH + part * 8];
            float4 b1 = *(const float4*)&b[m * DH + part * 8 + 4];
            float h[8];
            h[0] = acc[0] * inv + b0.x; h[1] = acc[1] * inv + b0.y;
            h[2] = acc[2] * inv + b0.z; h[3] = acc[3] * inv + b0.w;
            h[4] = acc[4] * inv + b1.x; h[5] = acc[5] * inv + b1.y;
            h[6] = acc[6] * inv + b1.z; h[7] = acc[7] * inv + b1.w;
#pragma unroll
            for (int j = 0; j < 8; j++) h[j] = (h[j] > 0.f) ? h[j] : a * h[j];
            ph[0] = __floats2half2_rn(h[0], h[1]);
            ph[1] = __floats2half2_rn(h[2], h[3]);
            ph[2] = __floats2half2_rn(h[4], h[5]);
            ph[3] = __floats2half2_rn(h[6], h[7]);
            *(uint4*)&g_hh[(size_t)p * DH + part * 8] = *(uint4*)ph;
        } else {
            ph[0] = ph[1] = ph[2] = ph[3] = __floats2half2_rn(0.f, 0.f);
        }
        *(uint4*)&sH[r * 72 + part * 8] = *(uint4*)ph;
    }
    __syncthreads();

    // ---- phase 2: MMA + epilogue (warps 0-3) ----
    if (wid < 4) {
        float c[8][4] = {};
        const int rowBase = wid * 16;
        unsigned hBase = (unsigned)__cvta_generic_to_shared(sH);
        unsigned wBase = (unsigned)__cvta_generic_to_shared(sW);

#pragma unroll
        for (int k0 = 0; k0 < 64; k0 += 16) {
            unsigned a0, a1, a2, a3;
            unsigned aAddr = hBase + (unsigned)(((rowBase + (lane & 15)) * 72 + k0 + ((lane >> 4) * 8)) * 2);
            asm volatile("ldmatrix.sync.aligned.m8n8.x4.shared.b16 {%0,%1,%2,%3}, [%4];"
                         : "=r"(a0), "=r"(a1), "=r"(a2), "=r"(a3) : "r"(aAddr));
#pragma unroll
            for (int nt = 0; nt < 8; nt++) {
                unsigned b0, b1;
                unsigned bAddr = wBase + (unsigned)(((k0 + (lane & 15)) * 72 + nt * 8) * 2);
                asm volatile("ldmatrix.sync.aligned.m8n8.x2.trans.shared.b16 {%0,%1}, [%2];"
                             : "=r"(b0), "=r"(b1) : "r"(bAddr));
                asm volatile("mma.sync.aligned.m16n8k16.row.col.f32.f16.f16.f32 "
                             "{%0,%1,%2,%3}, {%4,%5,%6,%7}, {%8,%9}, {%0,%1,%2,%3};"
                             : "+f"(c[nt][0]), "+f"(c[nt][1]), "+f"(c[nt][2]), "+f"(c[nt][3])
                             : "r"(a0), "r"(a1), "r"(a2), "r"(a3), "r"(b0), "r"(b1));
            }
        }

        int groupID = lane >> 2, tig = lane & 3;
        long long pr0 = p0 + rowBase + groupID;
        long long pr1 = pr0 + 8;
        float s0 = 0.f, s1 = 0.f;
#pragma unroll
        for (int nt = 0; nt < 8; nt++) {
            int col = nt * 8 + tig * 2;
            float fb0 = fc_b[col], fb1 = fc_b[col + 1];
            float av0 = attn[col], av1 = attn[col + 1];
            s0 += tanh_fast(c[nt][0] + fb0) * av0 + tanh_fast(c[nt][1] + fb1) * av1;
            s1 += tanh_fast(c[nt][2] + fb0) * av0 + tanh_fast(c[nt][3] + fb1) * av1;
        }
#pragma unroll
        for (int o = 1; o < 4; o <<= 1) {
            s0 += __shfl_xor_sync(0xffffffffu, s0, o);
            s1 += __shfl_xor_sync(0xffffffffu, s1, o);
        }
        if (tig == 0) {
            float c0 = (pr0 < NP) ? s0 : 0.f;
            float c1 = (pr1 < NP) ? s1 : 0.f;
            int mA = (int)(pr0 / NN), mB = (int)(pr1 / NN);
            float add0 = ((mA == m0) ? c0 : 0.f) + ((mB == m0) ? c1 : 0.f);
            float add1 = ((mA != m0) ? c0 : 0.f) + ((mB != m0) ? c1 : 0.f);
            if (add0 != 0.f) atomicAdd(&sLog[0], add0);
            if (add1 != 0.f) atomicAdd(&sLog[1], add1);
        }
    }
    __syncthreads();
    if (tid == 0) {
        if (sLog[0] != 0.f) atomicAdd(&g_logits[m0], sLog[0]);
        if (m0 + 1 < M3 && sLog[1] != 0.f) atomicAdd(&g_logits[m0 + 1], sLog[1]);
    }
}

// ---------------------------------------------------------------------------
// Kernel 4: beta = softmax(logits / N)
// ---------------------------------------------------------------------------
__global__ void beta_kernel() {
    if (threadIdx.x == 0) {
        float l0 = g_logits[0] / (float)NN;
        float l1 = g_logits[1] / (float)NN;
        float l2 = g_logits[2] / (float)NN;
        float mx = fmaxf(l0, fmaxf(l1, l2));
        float e0 = expf(l0 - mx), e1 = expf(l1 - mx), e2 = expf(l2 - mx);
        float s = e0 + e1 + e2;
        g_beta[0] = e0 / s; g_beta[1] = e1 / s; g_beta[2] = e2 / s;
    }
}

// ---------------------------------------------------------------------------
// Kernel 5: z[n][h] = sum_m beta[m] * h[m][n][h]   (fp16 h, fp32 out)
// ---------------------------------------------------------------------------
__global__ __launch_bounds__(256) void z_kernel(float* __restrict__ out) {
    size_t i = (size_t)blockIdx.x * blockDim.x + threadIdx.x;
    size_t tot = (size_t)NN * DH / 8;           // uint4 = 8 halves
    if (i >= tot) return;
    const size_t stride = (size_t)NN * DH / 8;
    float b0 = g_beta[0], b1 = g_beta[1], b2 = g_beta[2];
    uint4 u0 = ((const uint4*)g_hh)[i];
    uint4 u1 = ((const uint4*)g_hh)[i + stride];
    uint4 u2 = ((const uint4*)g_hh)[i + 2 * stride];
    float r[8];
#pragma unroll
    for (int j = 0; j < 4; j++) {
        float2 t0 = __half22float2(((__half2*)&u0)[j]);
        float2 t1 = __half22float2(((__half2*)&u1)[j]);
        float2 t2 = __half22float2(((__half2*)&u2)[j]);
        r[2 * j]     = b0 * t0.x + b1 * t1.x + b2 * t2.x;
        r[2 * j + 1] = b0 * t0.y + b1 * t1.y + b2 * t2.y;
    }
    float4* o = (float4*)out + i * 2;
    o[0] = make_float4(r[0], r[1], r[2], r[3]);
    o[1] = make_float4(r[4], r[5], r[6], r[7]);
}

// ---------------------------------------------------------------------------
extern "C" void kernel_launch(void* const* d_in, const int* in_sizes, int n_in,
                              void* d_out, int out_size) {
    const float* feats   = (const float*)d_in[0];
    const int*   src     = (const int*)  d_in[1];
    const int*   dst     = (const int*)  d_in[2];
    const float* W       = (const float*)d_in[3];
    const float* b       = (const float*)d_in[4];
    const float* prelu_a = (const float*)d_in[5];
    const float* fc_W    = (const float*)d_in[6];
    const float* fc_b    = (const float*)d_in[7];
    const float* attn    = (const float*)d_in[8];
    float* out = (float*)d_out;

    // Streams/events created ONCE (host-handle cache) -> no driver resource
    // creation during the capture call. Work per call is identical.
    static cudaStream_t s2;
    static cudaEvent_t evFork, evJoin;
    static bool s_init = false;
    if (!s_init) {
        cudaStreamCreateWithFlags(&s2, cudaStreamNonBlocking);
        cudaEventCreateWithFlags(&evFork, cudaEventDisableTiming);
        cudaEventCreateWithFlags(&evJoin, cudaEventDisableTiming);
        s_init = true;
    }

    // fork immediately: side chain (zero -> hist -> scans -> fill) runs
    // concurrently with proj on the main stream.
    cudaEventRecord(evFork, 0);
    cudaStreamWaitEvent(s2, evFork, 0);

    zero_kernel<<<(NP + 255) / 256, 256, 0, s2>>>();
    hist_kernel<<<(NET + 255) / 256, 256, 0, s2>>>(dst);
    scan1_kernel<<<SCAN_NBLK, 256, 0, s2>>>();
    scan2_kernel<<<1, 192, 0, s2>>>();
    scan3_kernel<<<SCAN_NBLK, 256, 0, s2>>>();
    fill_kernel<<<(NET + 255) / 256, 256, 0, s2>>>(src, dst);
    cudaEventRecord(evJoin, s2);

    // main chain: proj (overlaps with side chain)
    {
        dim3 grid((NN + 63) / 64, M3);
        proj_mma_kernel<<<grid, 128>>>(feats, W);
    }
    cudaStreamWaitEvent(0, evJoin, 0);

    // fused aggregate + finalize
    aggfin_kernel<<<(NP + 63) / 64, 512>>>(b, prelu_a, fc_W, fc_b, attn);
    beta_kernel<<<1, 32>>>();
    {
        size_t tot = (size_t)NN * DH / 8;
        z_kernel<<<(int)((tot + 255) / 256), 256>>>(out);
    }
}

// round 17
// speedup vs baseline: 1.1041x; 1.1041x over previous
#include <cuda_runtime.h>
#include <cuda_fp16.h>
#include <math.h>

#define NN   100000
#define M3   3
#define DIN  128
#define DH   64
#define NE   1600000
#define NP   300000                     // M3*NN rows
#define NET  4800000                    // M3*NE edges
#define SCAN_CHUNK 2048
#define SCAN_NBLK  147                  // ceil(NP/2048)

// ---- scratch (static device allocations; no cudaMalloc allowed) ----
__device__ __half g_projh[(size_t)NP * DH];      // [p][h] fp16
__device__ __half g_hh [(size_t)NP * DH];        // post-prelu h (fp16)
__device__ int   g_cnt [NP];
__device__ int   g_rowStart[NP];
__device__ int   g_cursor[NP];
__device__ int   g_eidx[NET];
__device__ int   g_blockSums[SCAN_NBLK];
__device__ int   g_blockOff [SCAN_NBLK];
__device__ float g_logits[M3];
__device__ float g_beta[M3];

__device__ __forceinline__ float tanh_fast(float x) {
    float y;
    asm("tanh.approx.f32 %0, %1;" : "=f"(y) : "f"(x));
    return y;
}

// ---------------------------------------------------------------------------
// Kernel 0: zero counters + logits
// ---------------------------------------------------------------------------
__global__ void zero_kernel() {
    int i = blockIdx.x * blockDim.x + threadIdx.x;
    if (i < NP) g_cnt[i] = 0;
    if (i < M3) g_logits[i] = 0.f;
}

// ---------------------------------------------------------------------------
// Kernel 1: proj via fp16 MMA (fp32 accum, fp16 out). 4 warps, 64x64 tile.
// ---------------------------------------------------------------------------
__global__ __launch_bounds__(128) void proj_mma_kernel(const float* __restrict__ feats,
                                                       const float* __restrict__ W) {
    __shared__ __align__(16) __half sA[64 * 136];
    __shared__ __align__(16) __half sW[128 * 72];
    const int m  = blockIdx.y;
    const int n0 = blockIdx.x * 64;
    const int tid = threadIdx.x;
    const int wid = tid >> 5, lane = tid & 31;
    const float* fbase = feats + (size_t)m * NN * DIN;
    const float* wbase = W + (size_t)m * DIN * DH;

    for (int i = tid; i < 64 * 64; i += 128) {
        int r = i >> 6, c2 = i & 63;
        float2 v = make_float2(0.f, 0.f);
        if (n0 + r < NN) v = *(const float2*)&fbase[(size_t)(n0 + r) * DIN + c2 * 2];
        *(__half2*)&sA[r * 136 + c2 * 2] = __floats2half2_rn(v.x, v.y);
    }
    for (int i = tid; i < 128 * 32; i += 128) {
        int r = i >> 5, c2 = i & 31;
        float2 v = *(const float2*)&wbase[(size_t)r * DH + c2 * 2];
        *(__half2*)&sW[r * 72 + c2 * 2] = __floats2half2_rn(v.x, v.y);
    }
    __syncthreads();

    float c[8][4] = {};
    const int rowBase = wid * 16;
    unsigned aBase = (unsigned)__cvta_generic_to_shared(sA);
    unsigned wBase = (unsigned)__cvta_generic_to_shared(sW);

#pragma unroll
    for (int k0 = 0; k0 < 128; k0 += 16) {
        unsigned a0, a1, a2, a3;
        unsigned aAddr = aBase + (unsigned)(((rowBase + (lane & 15)) * 136 + k0 + ((lane >> 4) * 8)) * 2);
        asm volatile("ldmatrix.sync.aligned.m8n8.x4.shared.b16 {%0,%1,%2,%3}, [%4];"
                     : "=r"(a0), "=r"(a1), "=r"(a2), "=r"(a3) : "r"(aAddr));
#pragma unroll
        for (int nt = 0; nt < 8; nt++) {
            unsigned b0, b1;
            unsigned bAddr = wBase + (unsigned)(((k0 + (lane & 15)) * 72 + nt * 8) * 2);
            asm volatile("ldmatrix.sync.aligned.m8n8.x2.trans.shared.b16 {%0,%1}, [%2];"
                         : "=r"(b0), "=r"(b1) : "r"(bAddr));
            asm volatile("mma.sync.aligned.m16n8k16.row.col.f32.f16.f16.f32 "
                         "{%0,%1,%2,%3}, {%4,%5,%6,%7}, {%8,%9}, {%0,%1,%2,%3};"
                         : "+f"(c[nt][0]), "+f"(c[nt][1]), "+f"(c[nt][2]), "+f"(c[nt][3])
                         : "r"(a0), "r"(a1), "r"(a2), "r"(a3), "r"(b0), "r"(b1));
        }
    }

    int groupID = lane >> 2, tig = lane & 3;
    int r0 = n0 + rowBase + groupID;
    int r1 = r0 + 8;
#pragma unroll
    for (int nt = 0; nt < 8; nt++) {
        int col = nt * 8 + tig * 2;
        if (r0 < NN)
            *(__half2*)&g_projh[((size_t)m * NN + r0) * DH + col] = __floats2half2_rn(c[nt][0], c[nt][1]);
        if (r1 < NN)
            *(__half2*)&g_projh[((size_t)m * NN + r1) * DH + col] = __floats2half2_rn(c[nt][2], c[nt][3]);
    }
}

// ---------------------------------------------------------------------------
// Kernel 2a: histogram of dst
// ---------------------------------------------------------------------------
__global__ __launch_bounds__(256) void hist_kernel(const int* __restrict__ dst) {
    int gid = blockIdx.x * blockDim.x + threadIdx.x;
    if (gid >= NET) return;
    int m = gid / NE;
    atomicAdd(&g_cnt[m * NN + dst[gid]], 1);
}

// ---------------------------------------------------------------------------
// Kernel 2b: per-chunk sums
// ---------------------------------------------------------------------------
__global__ __launch_bounds__(256) void scan1_kernel() {
    __shared__ int s[256];
    int tid = threadIdx.x;
    int base = blockIdx.x * SCAN_CHUNK + tid * 8;
    int sum = 0;
#pragma unroll
    for (int j = 0; j < 8; j++) {
        int i = base + j;
        if (i < NP) sum += g_cnt[i];
    }
    s[tid] = sum; __syncthreads();
    for (int off = 128; off; off >>= 1) {
        if (tid < off) s[tid] += s[tid + off];
        __syncthreads();
    }
    if (tid == 0) g_blockSums[blockIdx.x] = s[0];
}

// ---------------------------------------------------------------------------
// Kernel 2c: exclusive scan of 147 chunk sums — Hillis-Steele
// ---------------------------------------------------------------------------
__global__ __launch_bounds__(192) void scan2_kernel() {
    __shared__ int s[192];
    int tid = threadIdx.x;
    int v = (tid < SCAN_NBLK) ? g_blockSums[tid] : 0;
    s[tid] = v; __syncthreads();
    for (int off = 1; off < 192; off <<= 1) {
        int add = (tid >= off) ? s[tid - off] : 0;
        __syncthreads();
        s[tid] += add;
        __syncthreads();
    }
    if (tid < SCAN_NBLK) g_blockOff[tid] = s[tid] - v;   // exclusive
}

// ---------------------------------------------------------------------------
// Kernel 2d: per-chunk exclusive scan -> rowStart, cursor
// ---------------------------------------------------------------------------
__global__ __launch_bounds__(256) void scan3_kernel() {
    __shared__ int s[256];
    int tid = threadIdx.x;
    int base = blockIdx.x * SCAN_CHUNK + tid * 8;
    int cnt8[8];
    int sum = 0;
#pragma unroll
    for (int j = 0; j < 8; j++) {
        int i = base + j;
        cnt8[j] = (i < NP) ? g_cnt[i] : 0;
        sum += cnt8[j];
    }
    s[tid] = sum; __syncthreads();
    for (int off = 1; off < 256; off <<= 1) {
        int add = (tid >= off) ? s[tid - off] : 0;
        __syncthreads();
        s[tid] += add;
        __syncthreads();
    }
    int run = g_blockOff[blockIdx.x] + s[tid] - sum;
#pragma unroll
    for (int j = 0; j < 8; j++) {
        int i = base + j;
        if (i < NP) { g_rowStart[i] = run; g_cursor[i] = run; }
        run += cnt8[j];
    }
}

// ---------------------------------------------------------------------------
// Kernel 2e: fill buckets
// ---------------------------------------------------------------------------
__global__ __launch_bounds__(256) void fill_kernel(const int* __restrict__ src,
                                                   const int* __restrict__ dst) {
    int gid = blockIdx.x * blockDim.x + threadIdx.x;
    if (gid >= NET) return;
    int m = gid / NE;
    int pos = atomicAdd(&g_cursor[m * NN + dst[gid]], 1);
    g_eidx[pos] = m * NN + src[gid];
}

// ---------------------------------------------------------------------------
// Kernel 2f: pull-aggregate: 8 threads/node, uint4 fp16 gathers (plain loads).
// ---------------------------------------------------------------------------
__global__ __launch_bounds__(256) void aggregate_kernel(const float* __restrict__ b,
                                                        const float* __restrict__ prelu_a) {
    long long gid = (long long)blockIdx.x * blockDim.x + threadIdx.x;
    long long node8 = gid >> 3;
    if (node8 >= NP) return;
    int p = (int)node8;
    int part = (int)(gid & 7);          // owns cols [part*8, part*8+8)
    int rs = g_rowStart[p];
    int c  = g_cnt[p];

    float acc[8] = {};
    int e = rs, re = rs + c;
    for (; e + 1 < re; e += 2) {
        int i0 = g_eidx[e], i1 = g_eidx[e + 1];
        uint4 r0 = *(const uint4*)&g_projh[(size_t)i0 * DH + part * 8];
        uint4 r1 = *(const uint4*)&g_projh[(size_t)i1 * DH + part * 8];
        float2 t;
        t = __half22float2(*(__half2*)&r0.x); acc[0] += t.x; acc[1] += t.y;
        t = __half22float2(*(__half2*)&r0.y); acc[2] += t.x; acc[3] += t.y;
        t = __half22float2(*(__half2*)&r0.z); acc[4] += t.x; acc[5] += t.y;
        t = __half22float2(*(__half2*)&r0.w); acc[6] += t.x; acc[7] += t.y;
        t = __half22float2(*(__half2*)&r1.x); acc[0] += t.x; acc[1] += t.y;
        t = __half22float2(*(__half2*)&r1.y); acc[2] += t.x; acc[3] += t.y;
        t = __half22float2(*(__half2*)&r1.z); acc[4] += t.x; acc[5] += t.y;
        t = __half22float2(*(__half2*)&r1.w); acc[6] += t.x; acc[7] += t.y;
    }
    if (e < re) {
        int i0 = g_eidx[e];
        uint4 r0 = *(const uint4*)&g_projh[(size_t)i0 * DH + part * 8];
        float2 t;
        t = __half22float2(*(__half2*)&r0.x); acc[0] += t.x; acc[1] += t.y;
        t = __half22float2(*(__half2*)&r0.y); acc[2] += t.x; acc[3] += t.y;
        t = __half22float2(*(__half2*)&r0.z); acc[4] += t.x; acc[5] += t.y;
        t = __half22float2(*(__half2*)&r0.w); acc[6] += t.x; acc[7] += t.y;
    }
    int m = p / NN;
    float inv = 1.0f / (float)max(c, 1);
    float a = prelu_a[m];
    float4 b0 = *(const float4*)&b[m * DH + part * 8];
    float4 b1 = *(const float4*)&b[m * DH + part * 8 + 4];
    float h[8];
    h[0] = acc[0] * inv + b0.x; h[1] = acc[1] * inv + b0.y;
    h[2] = acc[2] * inv + b0.z; h[3] = acc[3] * inv + b0.w;
    h[4] = acc[4] * inv + b1.x; h[5] = acc[5] * inv + b1.y;
    h[6] = acc[6] * inv + b1.z; h[7] = acc[7] * inv + b1.w;
#pragma unroll
    for (int j = 0; j < 8; j++) h[j] = (h[j] > 0.f) ? h[j] : a * h[j];
    __half2 ph[4];
    ph[0] = __floats2half2_rn(h[0], h[1]);
    ph[1] = __floats2half2_rn(h[2], h[3]);
    ph[2] = __floats2half2_rn(h[4], h[5]);
    ph[3] = __floats2half2_rn(h[6], h[7]);
    *(uint4*)&g_hh[(size_t)p * DH + part * 8] = *(uint4*)ph;
}

// ---------------------------------------------------------------------------
// Kernel 3: finalize via fp16 MMA.
// ---------------------------------------------------------------------------
__global__ __launch_bounds__(128) void finalize_mma(const float* __restrict__ fc_W,
                                                    const float* __restrict__ fc_b,
                                                    const float* __restrict__ attn) {
    __shared__ __align__(16) __half sH[64 * 72];
    __shared__ __align__(16) __half sW[64 * 72];
    __shared__ float sLog[2];
    const int tid = threadIdx.x;
    const int wid = tid >> 5, lane = tid & 31;
    const long long p0 = (long long)blockIdx.x * 64;
    const int m0 = (int)(p0 / NN);

    for (int i = tid; i < 64 * 32; i += 128) {
        int r = i >> 5, c2 = i & 31;
        float2 v = *(const float2*)&fc_W[r * DH + c2 * 2];
        *(__half2*)&sW[r * 72 + c2 * 2] = __floats2half2_rn(v.x, v.y);
    }
    for (int i = tid; i < 64 * 8; i += 128) {
        int r = i >> 3, c4 = i & 7;
        long long p = p0 + r;
        uint4 v = make_uint4(0, 0, 0, 0);
        if (p < NP) v = *(const uint4*)&g_hh[(size_t)p * DH + c4 * 8];
        *(uint4*)&sH[r * 72 + c4 * 8] = v;
    }
    if (tid < 2) sLog[tid] = 0.f;
    __syncthreads();

    float c[8][4] = {};
    const int rowBase = wid * 16;
    unsigned hBase = (unsigned)__cvta_generic_to_shared(sH);
    unsigned wBase = (unsigned)__cvta_generic_to_shared(sW);

#pragma unroll
    for (int k0 = 0; k0 < 64; k0 += 16) {
        unsigned a0, a1, a2, a3;
        unsigned aAddr = hBase + (unsigned)(((rowBase + (lane & 15)) * 72 + k0 + ((lane >> 4) * 8)) * 2);
        asm volatile("ldmatrix.sync.aligned.m8n8.x4.shared.b16 {%0,%1,%2,%3}, [%4];"
                     : "=r"(a0), "=r"(a1), "=r"(a2), "=r"(a3) : "r"(aAddr));
#pragma unroll
        for (int nt = 0; nt < 8; nt++) {
            unsigned b0, b1;
            unsigned bAddr = wBase + (unsigned)(((k0 + (lane & 15)) * 72 + nt * 8) * 2);
            asm volatile("ldmatrix.sync.aligned.m8n8.x2.trans.shared.b16 {%0,%1}, [%2];"
                         : "=r"(b0), "=r"(b1) : "r"(bAddr));
            asm volatile("mma.sync.aligned.m16n8k16.row.col.f32.f16.f16.f32 "
                         "{%0,%1,%2,%3}, {%4,%5,%6,%7}, {%8,%9}, {%0,%1,%2,%3};"
                         : "+f"(c[nt][0]), "+f"(c[nt][1]), "+f"(c[nt][2]), "+f"(c[nt][3])
                         : "r"(a0), "r"(a1), "r"(a2), "r"(a3), "r"(b0), "r"(b1));
        }
    }

    int groupID = lane >> 2, tig = lane & 3;
    long long pr0 = p0 + rowBase + groupID;
    long long pr1 = pr0 + 8;
    float s0 = 0.f, s1 = 0.f;
#pragma unroll
    for (int nt = 0; nt < 8; nt++) {
        int col = nt * 8 + tig * 2;
        float fb0 = fc_b[col], fb1 = fc_b[col + 1];
        float av0 = attn[col], av1 = attn[col + 1];
        s0 += tanh_fast(c[nt][0] + fb0) * av0 + tanh_fast(c[nt][1] + fb1) * av1;
        s1 += tanh_fast(c[nt][2] + fb0) * av0 + tanh_fast(c[nt][3] + fb1) * av1;
    }
#pragma unroll
    for (int o = 1; o < 4; o <<= 1) {
        s0 += __shfl_xor_sync(0xffffffffu, s0, o);
        s1 += __shfl_xor_sync(0xffffffffu, s1, o);
    }
    if (tig == 0) {
        float c0 = (pr0 < NP) ? s0 : 0.f;
        float c1 = (pr1 < NP) ? s1 : 0.f;
        int mA = (int)(pr0 / NN), mB = (int)(pr1 / NN);
        float add0 = ((mA == m0) ? c0 : 0.f) + ((mB == m0) ? c1 : 0.f);
        float add1 = ((mA != m0) ? c0 : 0.f) + ((mB != m0) ? c1 : 0.f);
        if (add0 != 0.f) atomicAdd(&sLog[0], add0);
        if (add1 != 0.f) atomicAdd(&sLog[1], add1);
    }
    __syncthreads();
    if (tid == 0) {
        if (sLog[0] != 0.f) atomicAdd(&g_logits[m0], sLog[0]);
        if (m0 + 1 < M3 && sLog[1] != 0.f) atomicAdd(&g_logits[m0 + 1], sLog[1]);
    }
}

// ---------------------------------------------------------------------------
// Kernel 4: beta = softmax(logits / N)
// ---------------------------------------------------------------------------
__global__ void beta_kernel() {
    if (threadIdx.x == 0) {
        float l0 = g_logits[0] / (float)NN;
        float l1 = g_logits[1] / (float)NN;
        float l2 = g_logits[2] / (float)NN;
        float mx = fmaxf(l0, fmaxf(l1, l2));
        float e0 = expf(l0 - mx), e1 = expf(l1 - mx), e2 = expf(l2 - mx);
        float s = e0 + e1 + e2;
        g_beta[0] = e0 / s; g_beta[1] = e1 / s; g_beta[2] = e2 / s;
    }
}

// ---------------------------------------------------------------------------
// Kernel 5: z[n][h] = sum_m beta[m] * h[m][n][h]   (fp16 h, fp32 out)
// ---------------------------------------------------------------------------
__global__ __launch_bounds__(256) void z_kernel(float* __restrict__ out) {
    size_t i = (size_t)blockIdx.x * blockDim.x + threadIdx.x;
    size_t tot = (size_t)NN * DH / 8;           // uint4 = 8 halves
    if (i >= tot) return;
    const size_t stride = (size_t)NN * DH / 8;
    float b0 = g_beta[0], b1 = g_beta[1], b2 = g_beta[2];
    uint4 u0 = ((const uint4*)g_hh)[i];
    uint4 u1 = ((const uint4*)g_hh)[i + stride];
    uint4 u2 = ((const uint4*)g_hh)[i + 2 * stride];
    float r[8];
#pragma unroll
    for (int j = 0; j < 4; j++) {
        float2 t0 = __half22float2(((__half2*)&u0)[j]);
        float2 t1 = __half22float2(((__half2*)&u1)[j]);
        float2 t2 = __half22float2(((__half2*)&u2)[j]);
        r[2 * j]     = b0 * t0.x + b1 * t1.x + b2 * t2.x;
        r[2 * j + 1] = b0 * t0.y + b1 * t1.y + b2 * t2.y;
    }
    float4* o = (float4*)out + i * 2;
    o[0] = make_float4(r[0], r[1], r[2], r[3]);
    o[1] = make_float4(r[4], r[5], r[6], r[7]);
}

// ---------------------------------------------------------------------------
extern "C" void kernel_launch(void* const* d_in, const int* in_sizes, int n_in,
                              void* d_out, int out_size) {
    const float* feats   = (const float*)d_in[0];
    const int*   src     = (const int*)  d_in[1];
    const int*   dst     = (const int*)  d_in[2];
    const float* W       = (const float*)d_in[3];
    const float* b       = (const float*)d_in[4];
    const float* prelu_a = (const float*)d_in[5];
    const float* fc_W    = (const float*)d_in[6];
    const float* fc_b    = (const float*)d_in[7];
    const float* attn    = (const float*)d_in[8];
    float* out = (float*)d_out;

    // Streams/events created ONCE (host-handle cache) -> no driver resource
    // creation during the capture call. Work per call is identical.
    static cudaStream_t s2;
    static cudaEvent_t evFork, evJoin;
    static bool s_init = false;
    if (!s_init) {
        cudaStreamCreateWithFlags(&s2, cudaStreamNonBlocking);
        cudaEventCreateWithFlags(&evFork, cudaEventDisableTiming);
        cudaEventCreateWithFlags(&evJoin, cudaEventDisableTiming);
        s_init = true;
    }

    // fork immediately: side chain (zero -> hist -> scans -> fill) runs
    // concurrently with proj on the main stream.
    cudaEventRecord(evFork, 0);
    cudaStreamWaitEvent(s2, evFork, 0);

    zero_kernel<<<(NP + 255) / 256, 256, 0, s2>>>();
    hist_kernel<<<(NET + 255) / 256, 256, 0, s2>>>(dst);
    scan1_kernel<<<SCAN_NBLK, 256, 0, s2>>>();
    scan2_kernel<<<1, 192, 0, s2>>>();
    scan3_kernel<<<SCAN_NBLK, 256, 0, s2>>>();
    fill_kernel<<<(NET + 255) / 256, 256, 0, s2>>>(src, dst);
    cudaEventRecord(evJoin, s2);

    // main chain: proj (overlaps with side chain)
    {
        dim3 grid((NN + 63) / 64, M3);
        proj_mma_kernel<<<grid, 128>>>(feats, W);
    }
    cudaStreamWaitEvent(0, evJoin, 0);

    {
        long long threads = (long long)NP * 8;
        aggregate_kernel<<<(int)((threads + 255) / 256), 256>>>(b, prelu_a);
    }
    finalize_mma<<<(NP + 63) / 64, 128>>>(fc_W, fc_b, attn);
    beta_kernel<<<1, 32>>>();
    {
        size_t tot = (size_t)NN * DH / 8;
        z_kernel<<<(int)((tot + 255) / 256), 256>>>(out);
    }
}